// round 10
// baseline (speedup 1.0000x reference)
#include <cuda_runtime.h>
#include <math.h>
#include <float.h>

#define Bn   262144
#define Fdim 256
#define Kn   20
#define Hn   64
#define Mn   32
#define NPAIR 32640
#define GRID_A 148
#define GRID_B 148
#define TILE_A 64
#define TILE_B 256
#define KCHUNK 10
#define BK (Bn*Kn)

// ---------------- scratch (device globals; no runtime allocation) ----------------
__device__ float g_pairs[(size_t)2*Kn*Bn];  // [c][b], c = 2k + (0:pi,1:pj)
__device__ float g_ctx[(size_t)Kn*Bn];      // [k][b]
__device__ int   g_pi[Kn], g_pj[Kn];
__device__ float g_partial[GRID_A*Kn];

// ---------------- kernel 0: top-K pair selection ----------------
__global__ void k_topk(const float* __restrict__ IW, float* __restrict__ out)
{
    extern __shared__ char sm[];
    float* sw   = (float*)sm;                                // NPAIR floats
    float* rw   = (float*)(sm + NPAIR*4);                    // 1024
    int*   rp   = (int*)  (sm + NPAIR*4 + 4096);             // 1024
    int*   sel  = (int*)  (sm + NPAIR*4 + 8192);             // 20
    float* vsel = (float*)(sm + NPAIR*4 + 8192 + 80);        // 20
    int tid = threadIdx.x;

    for (int q = tid; q < Fdim*Fdim; q += 1024) {
        int i = q >> 8, j = q & 255;
        if (j > i) {
            int p = i*255 - (i*(i-1))/2 + (j - i - 1);
            sw[p] = IW[q];
        }
    }
    __syncthreads();

    for (int r = 0; r < Kn; r++) {
        float bw = -FLT_MAX; int bp = 1 << 30;
        for (int p = tid; p < NPAIR; p += 1024) {
            bool taken = false;
            for (int t = 0; t < r; t++) taken |= (sel[t] == p);
            if (!taken) {
                float w = sw[p];
                if (w > bw || (w == bw && p < bp)) { bw = w; bp = p; }
            }
        }
        rw[tid] = bw; rp[tid] = bp;
        __syncthreads();
        for (int s = 512; s > 0; s >>= 1) {
            if (tid < s) {
                float w2 = rw[tid+s]; int p2 = rp[tid+s];
                if (w2 > rw[tid] || (w2 == rw[tid] && p2 < rp[tid])) { rw[tid] = w2; rp[tid] = p2; }
            }
            __syncthreads();
        }
        if (tid == 0) sel[r] = rp[0];
        __syncthreads();
    }

    if (tid < Kn) {
        int p = sel[tid];
        int rem = p, i = 0;
        while (rem >= 255 - i) { rem -= 255 - i; i++; }
        int j = i + 1 + rem;
        g_pi[tid] = i; g_pj[tid] = j;
        float v = 1.0f / (1.0f + expf(-sw[p]));
        vsel[tid] = v;
        out[BK + tid] = v;                                   // importances
        out[BK + 2*Kn + 1 + 2*tid]     = (float)i;           // selected_pairs
        out[BK + 2*Kn + 1 + 2*tid + 1] = (float)j;
    }
    __syncthreads();
    if (tid == 0) {
        int cnt = 0;
        for (int t = 0; t < Kn; t++) cnt += (vsel[t] > 0.1f);
        out[BK + 2*Kn] = (float)cnt;                         // active_interactions
    }
}

// ---------------- kernel A: ctx network + pair gather (512 thr) ----------------
__global__ void __launch_bounds__(512,1) k_ctx(
    const float* __restrict__ x,   const float* __restrict__ Wc1,
    const float* __restrict__ bc1, const float* __restrict__ Wc2,
    const float* __restrict__ bc2)
{
    extern __shared__ char sm[];
    float* Wc1s = (float*)sm;            // 16384
    float* xs   = Wc1s + 16384;          // 256*66 = 16896 (transposed [f][r], pad 66)
    float* hs   = xs + 16896;            // 64*65 = 4160
    float* Wc2s = hs + 4160;             // 1280
    float* ctxs = Wc2s + 1280;           // 1280
    float* bc1s = ctxs + 1280;           // 64
    float* bc2s = bc1s + 64;             // 20
    float* bsum = bc2s + 20;             // 20
    int*   pcols = (int*)(bsum + 20);    // 40

    int tid = threadIdx.x;
    for (int idx = tid; idx < Fdim*Hn; idx += 512) Wc1s[idx] = Wc1[idx];
    for (int idx = tid; idx < Hn*Kn;  idx += 512) Wc2s[idx] = Wc2[idx];
    if (tid < Hn)   bc1s[tid] = bc1[tid];
    if (tid < Kn) { bc2s[tid] = bc2[tid]; bsum[tid] = 0.0f; }
    if (tid < 2*Kn) pcols[tid] = (tid & 1) ? g_pj[tid>>1] : g_pi[tid>>1];
    __syncthreads();

    int tr = tid >> 4, tc = tid & 15;    // tr 0..31 (2 rows), tc 0..15 (4 cols)
    int f0 = tid & 255, half = tid >> 8; // for x staging
    for (int tile = blockIdx.x; tile < Bn/TILE_A; tile += GRID_A) {
        int b0 = tile * TILE_A;
        // stage x tile, transposed: xs[f][r]
        #pragma unroll 4
        for (int ii = 0; ii < 32; ii++) {
            int r = half*32 + ii;
            xs[f0*66 + r] = x[(b0 + r)*Fdim + f0];
        }
        __syncthreads();

        // GEMM1: thread computes 2 rows x 4 cols
        float acc[2][4];
        #pragma unroll
        for (int i = 0; i < 2; i++)
            #pragma unroll
            for (int j = 0; j < 4; j++) acc[i][j] = 0.f;

        #pragma unroll 4
        for (int f = 0; f < Fdim; f++) {
            float2 a  = *(float2*)&xs[f*66 + tr*2];
            float4 bv = *(float4*)&Wc1s[f*64 + tc*4];
            acc[0][0] += a.x*bv.x; acc[0][1] += a.x*bv.y; acc[0][2] += a.x*bv.z; acc[0][3] += a.x*bv.w;
            acc[1][0] += a.y*bv.x; acc[1][1] += a.y*bv.y; acc[1][2] += a.y*bv.z; acc[1][3] += a.y*bv.w;
        }
        #pragma unroll
        for (int i = 0; i < 2; i++)
            #pragma unroll
            for (int j = 0; j < 4; j++)
                hs[(tr*2+i)*65 + tc*4+j] = fmaxf(acc[i][j] + bc1s[tc*4+j], 0.f);
        __syncthreads();

        // layer 2 + sigmoid: ctx[64][20]
        for (int idx = tid; idx < TILE_A*Kn; idx += 512) {
            int r = idx / Kn, k = idx - r*Kn;
            float s = bc2s[k];
            #pragma unroll 8
            for (int h = 0; h < Hn; h++) s += hs[r*65 + h] * Wc2s[h*Kn + k];
            ctxs[idx] = 1.0f / (1.0f + expf(-s));
        }
        __syncthreads();

        // coalesced k-major ctx write
        for (int idx = tid; idx < TILE_A*Kn; idx += 512) {
            int kk = idx >> 6, r = idx & 63;
            g_ctx[kk*Bn + b0 + r] = ctxs[r*Kn + kk];
        }
        // coalesced c-major pair gather
        #pragma unroll
        for (int ii = 0; ii < 5; ii++) {
            int idx = tid + 512*ii;          // < 2560
            int c = idx >> 6, r = idx & 63;
            g_pairs[c*Bn + b0 + r] = xs[pcols[c]*66 + r];
        }
        // ctx mean partials
        if (tid < Kn) {
            float s = 0.f;
            for (int r = 0; r < TILE_A; r++) s += ctxs[r*Kn + tid];
            bsum[tid] += s;
        }
        __syncthreads();
    }
    if (tid < Kn) g_partial[blockIdx.x*Kn + tid] = bsum[tid];
}

// ---------------- kernel C: ctx mean finalize ----------------
__global__ void k_mean(float* __restrict__ out)
{
    int t = threadIdx.x;
    if (t < Kn) {
        double s = 0.0;
        for (int i = 0; i < GRID_A; i++) s += (double)g_partial[i*Kn + t];
        out[BK + Kn + t] = (float)(s / (double)Bn);
    }
}

// ---------------- kernel B: K stacked pair MLPs (512 thr, W2 in 2 k-chunks) ----------------
__global__ void __launch_bounds__(512,1) k_mlp(
    const float* __restrict__ W1, const float* __restrict__ b1,
    const float* __restrict__ W2, const float* __restrict__ b2,
    const float* __restrict__ W3, const float* __restrict__ b3,
    float* __restrict__ out)
{
    extern __shared__ char sm[];
    float* W2s  = (float*)sm;        // KCHUNK*2048 = 20480
    float* h1s  = W2s + 20480;       // 64*256 = 16384 ([h][r])
    float* outs = h1s + 16384;       // 256*10 = 2560
    float* W1s  = outs + 2560;       // 2560
    float* b1s  = W1s + 2560;        // 1280
    float* b2s  = b1s + 1280;        // 640
    float* W3s  = b2s + 640;         // 640
    float* b3s  = W3s + 640;         // 20

    int tid = threadIdx.x;
    for (int idx = tid; idx < Kn*2*Hn;  idx += 512) W1s[idx] = W1[idx];
    for (int idx = tid; idx < Kn*Hn;    idx += 512) b1s[idx] = b1[idx];
    for (int idx = tid; idx < Kn*Mn;    idx += 512) { b2s[idx] = b2[idx]; W3s[idx] = W3[idx]; }
    if (tid < Kn) b3s[tid] = b3[tid];

    int mg = tid & 3, rg = tid >> 2;     // 4 m-groups x 128 row-groups
    int m0 = mg * 8,  r0 = rg * 2;       // rows 0..255, m 0..31
    int rr = tid & 255, hh = tid >> 8;   // for h1 stage

    for (int c = 0; c < 2; c++) {
        int koff = c * KCHUNK;
        __syncthreads();                 // protect W2s reuse across chunks
        for (int idx = tid; idx < KCHUNK*Hn*Mn; idx += 512)
            W2s[idx] = W2[koff*Hn*Mn + idx];
        __syncthreads();

        for (int tile = blockIdx.x; tile < Bn/TILE_B; tile += GRID_B) {
            int b0 = tile * TILE_B;
            for (int kk = 0; kk < KCHUNK; kk++) {
                int k = koff + kk;
                // h1[h][r] = relu(p0*W1[k,0,h] + p1*W1[k,1,h] + b1[k,h])
                {
                    float p0 = g_pairs[(2*k)*Bn   + b0 + rr];
                    float p1 = g_pairs[(2*k+1)*Bn + b0 + rr];
                    const float* W1k = W1s + k*128;
                    const float* b1k = b1s + k*64;
                    #pragma unroll 8
                    for (int ii = 0; ii < 32; ii++) {
                        int h = hh*32 + ii;
                        float v = fmaf(p0, W1k[h], fmaf(p1, W1k[64 + h], b1k[h]));
                        h1s[h*256 + rr] = fmaxf(v, 0.f);
                    }
                }
                __syncthreads();
                // GEMM: C[256][32] = h1s^T @ W2[k]; thread = 2 rows x 8 m
                float acc[2][8];
                #pragma unroll
                for (int j = 0; j < 8; j++) { acc[0][j] = 0.f; acc[1][j] = 0.f; }
                const float* W2k = W2s + kk*2048;
                #pragma unroll 4
                for (int h = 0; h < Hn; h++) {
                    float2 a  = *(float2*)&h1s[h*256 + r0];
                    float4 w0 = *(float4*)&W2k[h*32 + m0];
                    float4 w1 = *(float4*)&W2k[h*32 + m0 + 4];
                    acc[0][0] += a.x*w0.x; acc[0][1] += a.x*w0.y; acc[0][2] += a.x*w0.z; acc[0][3] += a.x*w0.w;
                    acc[0][4] += a.x*w1.x; acc[0][5] += a.x*w1.y; acc[0][6] += a.x*w1.z; acc[0][7] += a.x*w1.w;
                    acc[1][0] += a.y*w0.x; acc[1][1] += a.y*w0.y; acc[1][2] += a.y*w0.z; acc[1][3] += a.y*w0.w;
                    acc[1][4] += a.y*w1.x; acc[1][5] += a.y*w1.y; acc[1][6] += a.y*w1.z; acc[1][7] += a.y*w1.w;
                }
                // epilogue: relu(+b2), dot W3, quad-reduce, + b3, * ctx
                float s0 = 0.f, s1 = 0.f;
                #pragma unroll
                for (int j = 0; j < 8; j++) {
                    float bb = b2s[k*32 + m0 + j];
                    float w3 = W3s[k*32 + m0 + j];
                    s0 += fmaxf(acc[0][j] + bb, 0.f) * w3;
                    s1 += fmaxf(acc[1][j] + bb, 0.f) * w3;
                }
                s0 += __shfl_xor_sync(0xffffffffu, s0, 1);
                s0 += __shfl_xor_sync(0xffffffffu, s0, 2);
                s1 += __shfl_xor_sync(0xffffffffu, s1, 1);
                s1 += __shfl_xor_sync(0xffffffffu, s1, 2);
                if (mg == 0) {
                    float2 c2 = *(float2*)&g_ctx[k*Bn + b0 + r0];
                    float bb3 = b3s[k];
                    outs[r0*KCHUNK + kk]     = (s0 + bb3) * c2.x;
                    outs[(r0+1)*KCHUNK + kk] = (s1 + bb3) * c2.y;
                }
                __syncthreads();     // h1s / outs reuse
            }
            // write this chunk's outputs: out[(b0+r)*20 + koff + kk]
            #pragma unroll
            for (int ii = 0; ii < 5; ii++) {
                int idx = tid + 512*ii;              // < 2560
                int r = idx / KCHUNK, kk = idx - r*KCHUNK;
                out[(b0 + r)*Kn + koff + kk] = outs[idx];
            }
            __syncthreads();
        }
    }
}

// ---------------- launch ----------------
extern "C" void kernel_launch(void* const* d_in, const int* in_sizes, int n_in,
                              void* d_out, int out_size)
{
    const float* x   = (const float*)d_in[0];
    const float* IW  = (const float*)d_in[1];
    const float* Wc1 = (const float*)d_in[2];
    const float* bc1 = (const float*)d_in[3];
    const float* Wc2 = (const float*)d_in[4];
    const float* bc2 = (const float*)d_in[5];
    const float* W1  = (const float*)d_in[6];
    const float* b1  = (const float*)d_in[7];
    const float* W2  = (const float*)d_in[8];
    const float* b2  = (const float*)d_in[9];
    const float* W3  = (const float*)d_in[10];
    const float* b3  = (const float*)d_in[11];
    float* out = (float*)d_out;

    const int smem0 = NPAIR*4 + 4096 + 4096 + 80 + 80;   // 138,912 B
    const int smemA = 40144 * 4;                          // 160,576 B
    const int smemB = 44564 * 4;                          // 178,256 B

    cudaFuncSetAttribute(k_topk, cudaFuncAttributeMaxDynamicSharedMemorySize, smem0);
    cudaFuncSetAttribute(k_ctx,  cudaFuncAttributeMaxDynamicSharedMemorySize, smemA);
    cudaFuncSetAttribute(k_mlp,  cudaFuncAttributeMaxDynamicSharedMemorySize, smemB);

    // order chosen so the fixed ncu skip window lands on k_mlp (was k_mean)
    k_topk<<<1, 1024, smem0>>>(IW, out);
    k_ctx <<<GRID_A, 512, smemA>>>(x, Wc1, bc1, Wc2, bc2);
    k_mean<<<1, 32>>>(out);
    k_mlp <<<GRID_B, 512, smemB>>>(W1, b1, W2, b2, W3, b3, out);
}

// round 11
// speedup vs baseline: 1.0018x; 1.0018x over previous
#include <cuda_runtime.h>
#include <math.h>
#include <float.h>

#define Bn   262144
#define Fdim 256
#define Kn   20
#define Hn   64
#define Mn   32
#define NPAIR 32640
#define GRID_A 148
#define GRID_B 148
#define TILE_A 64
#define TILE_B 256
#define KCHUNK 10
#define BK (Bn*Kn)

// ---------------- scratch (device globals; no runtime allocation) ----------------
__device__ float g_pairs[(size_t)2*Kn*Bn];  // [c][b], c = 2k + (0:pi,1:pj)
__device__ float g_ctx[(size_t)Kn*Bn];      // [k][b]
__device__ int   g_pi[Kn], g_pj[Kn];
__device__ float g_partial[GRID_A*Kn];

// ---------------- kernel 0: top-K pair selection ----------------
__global__ void k_topk(const float* __restrict__ IW, float* __restrict__ out)
{
    extern __shared__ char sm[];
    float* sw   = (float*)sm;                                // NPAIR floats
    float* rw   = (float*)(sm + NPAIR*4);                    // 1024
    int*   rp   = (int*)  (sm + NPAIR*4 + 4096);             // 1024
    int*   sel  = (int*)  (sm + NPAIR*4 + 8192);             // 20
    float* vsel = (float*)(sm + NPAIR*4 + 8192 + 80);        // 20
    int tid = threadIdx.x;

    for (int q = tid; q < Fdim*Fdim; q += 1024) {
        int i = q >> 8, j = q & 255;
        if (j > i) {
            int p = i*255 - (i*(i-1))/2 + (j - i - 1);
            sw[p] = IW[q];
        }
    }
    __syncthreads();

    for (int r = 0; r < Kn; r++) {
        float bw = -FLT_MAX; int bp = 1 << 30;
        for (int p = tid; p < NPAIR; p += 1024) {
            bool taken = false;
            for (int t = 0; t < r; t++) taken |= (sel[t] == p);
            if (!taken) {
                float w = sw[p];
                if (w > bw || (w == bw && p < bp)) { bw = w; bp = p; }
            }
        }
        rw[tid] = bw; rp[tid] = bp;
        __syncthreads();
        for (int s = 512; s > 0; s >>= 1) {
            if (tid < s) {
                float w2 = rw[tid+s]; int p2 = rp[tid+s];
                if (w2 > rw[tid] || (w2 == rw[tid] && p2 < rp[tid])) { rw[tid] = w2; rp[tid] = p2; }
            }
            __syncthreads();
        }
        if (tid == 0) sel[r] = rp[0];
        __syncthreads();
    }

    if (tid < Kn) {
        int p = sel[tid];
        int rem = p, i = 0;
        while (rem >= 255 - i) { rem -= 255 - i; i++; }
        int j = i + 1 + rem;
        g_pi[tid] = i; g_pj[tid] = j;
        float v = 1.0f / (1.0f + expf(-sw[p]));
        vsel[tid] = v;
        out[BK + tid] = v;                                   // importances
        out[BK + 2*Kn + 1 + 2*tid]     = (float)i;           // selected_pairs
        out[BK + 2*Kn + 1 + 2*tid + 1] = (float)j;
    }
    __syncthreads();
    if (tid == 0) {
        int cnt = 0;
        for (int t = 0; t < Kn; t++) cnt += (vsel[t] > 0.1f);
        out[BK + 2*Kn] = (float)cnt;                         // active_interactions
    }
}

// ---------------- kernel A: ctx network + pair gather (512 thr) ----------------
__global__ void __launch_bounds__(512,1) k_ctx(
    const float* __restrict__ x,   const float* __restrict__ Wc1,
    const float* __restrict__ bc1, const float* __restrict__ Wc2,
    const float* __restrict__ bc2)
{
    extern __shared__ char sm[];
    float* Wc1s = (float*)sm;            // 16384
    float* xs   = Wc1s + 16384;          // 256*66 = 16896 (transposed [f][r], pad 66)
    float* hs   = xs + 16896;            // 64*65 = 4160
    float* Wc2s = hs + 4160;             // 1280
    float* ctxs = Wc2s + 1280;           // 1280
    float* bc1s = ctxs + 1280;           // 64
    float* bc2s = bc1s + 64;             // 20
    float* bsum = bc2s + 20;             // 20
    int*   pcols = (int*)(bsum + 20);    // 40

    int tid = threadIdx.x;
    for (int idx = tid; idx < Fdim*Hn; idx += 512) Wc1s[idx] = Wc1[idx];
    for (int idx = tid; idx < Hn*Kn;  idx += 512) Wc2s[idx] = Wc2[idx];
    if (tid < Hn)   bc1s[tid] = bc1[tid];
    if (tid < Kn) { bc2s[tid] = bc2[tid]; bsum[tid] = 0.0f; }
    if (tid < 2*Kn) pcols[tid] = (tid & 1) ? g_pj[tid>>1] : g_pi[tid>>1];
    __syncthreads();

    int tr = tid >> 4, tc = tid & 15;    // tr 0..31 (2 rows), tc 0..15 (4 cols)
    int f0 = tid & 255, half = tid >> 8; // for x staging
    for (int tile = blockIdx.x; tile < Bn/TILE_A; tile += GRID_A) {
        int b0 = tile * TILE_A;
        // stage x tile, transposed: xs[f][r]
        #pragma unroll 4
        for (int ii = 0; ii < 32; ii++) {
            int r = half*32 + ii;
            xs[f0*66 + r] = x[(b0 + r)*Fdim + f0];
        }
        __syncthreads();

        // GEMM1: thread computes 2 rows x 4 cols
        float acc[2][4];
        #pragma unroll
        for (int i = 0; i < 2; i++)
            #pragma unroll
            for (int j = 0; j < 4; j++) acc[i][j] = 0.f;

        #pragma unroll 4
        for (int f = 0; f < Fdim; f++) {
            float2 a  = *(float2*)&xs[f*66 + tr*2];
            float4 bv = *(float4*)&Wc1s[f*64 + tc*4];
            acc[0][0] += a.x*bv.x; acc[0][1] += a.x*bv.y; acc[0][2] += a.x*bv.z; acc[0][3] += a.x*bv.w;
            acc[1][0] += a.y*bv.x; acc[1][1] += a.y*bv.y; acc[1][2] += a.y*bv.z; acc[1][3] += a.y*bv.w;
        }
        #pragma unroll
        for (int i = 0; i < 2; i++)
            #pragma unroll
            for (int j = 0; j < 4; j++)
                hs[(tr*2+i)*65 + tc*4+j] = fmaxf(acc[i][j] + bc1s[tc*4+j], 0.f);
        __syncthreads();

        // layer 2 + sigmoid: ctx[64][20]
        for (int idx = tid; idx < TILE_A*Kn; idx += 512) {
            int r = idx / Kn, k = idx - r*Kn;
            float s = bc2s[k];
            #pragma unroll 8
            for (int h = 0; h < Hn; h++) s += hs[r*65 + h] * Wc2s[h*Kn + k];
            ctxs[idx] = 1.0f / (1.0f + expf(-s));
        }
        __syncthreads();

        // coalesced k-major ctx write
        for (int idx = tid; idx < TILE_A*Kn; idx += 512) {
            int kk = idx >> 6, r = idx & 63;
            g_ctx[kk*Bn + b0 + r] = ctxs[r*Kn + kk];
        }
        // coalesced c-major pair gather
        #pragma unroll
        for (int ii = 0; ii < 5; ii++) {
            int idx = tid + 512*ii;          // < 2560
            int c = idx >> 6, r = idx & 63;
            g_pairs[c*Bn + b0 + r] = xs[pcols[c]*66 + r];
        }
        // ctx mean partials
        if (tid < Kn) {
            float s = 0.f;
            for (int r = 0; r < TILE_A; r++) s += ctxs[r*Kn + tid];
            bsum[tid] += s;
        }
        __syncthreads();
    }
    if (tid < Kn) g_partial[blockIdx.x*Kn + tid] = bsum[tid];
}

// ---------------- kernel C: ctx mean finalize ----------------
__global__ void k_mean(float* __restrict__ out)
{
    int t = threadIdx.x;
    if (t < Kn) {
        double s = 0.0;
        for (int i = 0; i < GRID_A; i++) s += (double)g_partial[i*Kn + t];
        out[BK + Kn + t] = (float)(s / (double)Bn);
    }
}

// ---------------- kernel B: K stacked pair MLPs (512 thr, W2 in 2 k-chunks) ----------------
__global__ void __launch_bounds__(512,1) k_mlp(
    const float* __restrict__ W1, const float* __restrict__ b1,
    const float* __restrict__ W2, const float* __restrict__ b2,
    const float* __restrict__ W3, const float* __restrict__ b3,
    float* __restrict__ out)
{
    extern __shared__ char sm[];
    float* W2s  = (float*)sm;        // KCHUNK*2048 = 20480
    float* h1s  = W2s + 20480;       // 64*256 = 16384 ([h][r])
    float* outs = h1s + 16384;       // 256*10 = 2560
    float* W1s  = outs + 2560;       // 2560
    float* b1s  = W1s + 2560;        // 1280
    float* b2s  = b1s + 1280;        // 640
    float* W3s  = b2s + 640;         // 640
    float* b3s  = W3s + 640;         // 20

    int tid = threadIdx.x;
    for (int idx = tid; idx < Kn*2*Hn;  idx += 512) W1s[idx] = W1[idx];
    for (int idx = tid; idx < Kn*Hn;    idx += 512) b1s[idx] = b1[idx];
    for (int idx = tid; idx < Kn*Mn;    idx += 512) { b2s[idx] = b2[idx]; W3s[idx] = W3[idx]; }
    if (tid < Kn) b3s[tid] = b3[tid];

    int mg = tid & 3, rg = tid >> 2;     // 4 m-groups x 128 row-groups
    int m0 = mg * 8,  r0 = rg * 2;       // rows 0..255, m 0..31
    int rr = tid & 255, hh = tid >> 8;   // for h1 stage

    for (int c = 0; c < 2; c++) {
        int koff = c * KCHUNK;
        __syncthreads();                 // protect W2s reuse across chunks
        for (int idx = tid; idx < KCHUNK*Hn*Mn; idx += 512)
            W2s[idx] = W2[koff*Hn*Mn + idx];
        __syncthreads();

        for (int tile = blockIdx.x; tile < Bn/TILE_B; tile += GRID_B) {
            int b0 = tile * TILE_B;
            for (int kk = 0; kk < KCHUNK; kk++) {
                int k = koff + kk;
                // h1[h][r] = relu(p0*W1[k,0,h] + p1*W1[k,1,h] + b1[k,h])
                {
                    float p0 = g_pairs[(2*k)*Bn   + b0 + rr];
                    float p1 = g_pairs[(2*k+1)*Bn + b0 + rr];
                    const float* W1k = W1s + k*128;
                    const float* b1k = b1s + k*64;
                    #pragma unroll 8
                    for (int ii = 0; ii < 32; ii++) {
                        int h = hh*32 + ii;
                        float v = fmaf(p0, W1k[h], fmaf(p1, W1k[64 + h], b1k[h]));
                        h1s[h*256 + rr] = fmaxf(v, 0.f);
                    }
                }
                __syncthreads();
                // GEMM: C[256][32] = h1s^T @ W2[k]; thread = 2 rows x 8 m
                float acc[2][8];
                #pragma unroll
                for (int j = 0; j < 8; j++) { acc[0][j] = 0.f; acc[1][j] = 0.f; }
                const float* W2k = W2s + kk*2048;
                #pragma unroll 4
                for (int h = 0; h < Hn; h++) {
                    float2 a  = *(float2*)&h1s[h*256 + r0];
                    float4 w0 = *(float4*)&W2k[h*32 + m0];
                    float4 w1 = *(float4*)&W2k[h*32 + m0 + 4];
                    acc[0][0] += a.x*w0.x; acc[0][1] += a.x*w0.y; acc[0][2] += a.x*w0.z; acc[0][3] += a.x*w0.w;
                    acc[0][4] += a.x*w1.x; acc[0][5] += a.x*w1.y; acc[0][6] += a.x*w1.z; acc[0][7] += a.x*w1.w;
                    acc[1][0] += a.y*w0.x; acc[1][1] += a.y*w0.y; acc[1][2] += a.y*w0.z; acc[1][3] += a.y*w0.w;
                    acc[1][4] += a.y*w1.x; acc[1][5] += a.y*w1.y; acc[1][6] += a.y*w1.z; acc[1][7] += a.y*w1.w;
                }
                // epilogue: relu(+b2), dot W3, quad-reduce, + b3, * ctx
                float s0 = 0.f, s1 = 0.f;
                #pragma unroll
                for (int j = 0; j < 8; j++) {
                    float bb = b2s[k*32 + m0 + j];
                    float w3 = W3s[k*32 + m0 + j];
                    s0 += fmaxf(acc[0][j] + bb, 0.f) * w3;
                    s1 += fmaxf(acc[1][j] + bb, 0.f) * w3;
                }
                s0 += __shfl_xor_sync(0xffffffffu, s0, 1);
                s0 += __shfl_xor_sync(0xffffffffu, s0, 2);
                s1 += __shfl_xor_sync(0xffffffffu, s1, 1);
                s1 += __shfl_xor_sync(0xffffffffu, s1, 2);
                if (mg == 0) {
                    float2 c2 = *(float2*)&g_ctx[k*Bn + b0 + r0];
                    float bb3 = b3s[k];
                    outs[r0*KCHUNK + kk]     = (s0 + bb3) * c2.x;
                    outs[(r0+1)*KCHUNK + kk] = (s1 + bb3) * c2.y;
                }
                __syncthreads();     // h1s / outs reuse
            }
            // write this chunk's outputs: out[(b0+r)*20 + koff + kk]
            #pragma unroll
            for (int ii = 0; ii < 5; ii++) {
                int idx = tid + 512*ii;              // < 2560
                int r = idx / KCHUNK, kk = idx - r*KCHUNK;
                out[(b0 + r)*Kn + koff + kk] = outs[idx];
            }
            __syncthreads();
        }
    }
}

// ---------------- launch ----------------
extern "C" void kernel_launch(void* const* d_in, const int* in_sizes, int n_in,
                              void* d_out, int out_size)
{
    const float* x   = (const float*)d_in[0];
    const float* IW  = (const float*)d_in[1];
    const float* Wc1 = (const float*)d_in[2];
    const float* bc1 = (const float*)d_in[3];
    const float* Wc2 = (const float*)d_in[4];
    const float* bc2 = (const float*)d_in[5];
    const float* W1  = (const float*)d_in[6];
    const float* b1  = (const float*)d_in[7];
    const float* W2  = (const float*)d_in[8];
    const float* b2  = (const float*)d_in[9];
    const float* W3  = (const float*)d_in[10];
    const float* b3  = (const float*)d_in[11];
    float* out = (float*)d_out;

    const int smem0 = NPAIR*4 + 4096 + 4096 + 80 + 80;   // 138,912 B
    const int smemA = 40144 * 4;                          // 160,576 B
    const int smemB = 44564 * 4;                          // 178,256 B

    cudaFuncSetAttribute(k_topk, cudaFuncAttributeMaxDynamicSharedMemorySize, smem0);
    cudaFuncSetAttribute(k_ctx,  cudaFuncAttributeMaxDynamicSharedMemorySize, smemA);
    cudaFuncSetAttribute(k_mlp,  cudaFuncAttributeMaxDynamicSharedMemorySize, smemB);

    // order chosen so the fixed ncu skip window lands on k_mlp (was k_mean)
    k_topk<<<1, 1024, smem0>>>(IW, out);
    k_ctx <<<GRID_A, 512, smemA>>>(x, Wc1, bc1, Wc2, bc2);
    k_mean<<<1, 32>>>(out);
    k_mlp <<<GRID_B, 512, smemB>>>(W1, b1, W2, b2, W3, b3, out);
}

// round 12
// speedup vs baseline: 1.0063x; 1.0045x over previous
#include <cuda_runtime.h>
#include <math.h>
#include <float.h>

#define Bn   262144
#define Fdim 256
#define Kn   20
#define Hn   64
#define Mn   32
#define NPAIR 32640
#define GRID_A 148
#define GRID_B 148
#define TILE_A 64
#define TILE_B 256
#define KCHUNK 10
#define BK (Bn*Kn)

// ---------------- scratch (device globals; no runtime allocation) ----------------
__device__ float g_pairs[(size_t)2*Kn*Bn];  // [c][b], c = 2k + (0:pi,1:pj)
__device__ float g_ctx[(size_t)Kn*Bn];      // [k][b]
__device__ int   g_pi[Kn], g_pj[Kn];
__device__ float g_partial[GRID_A*Kn];

// ---------------- kernel 0: top-K pair selection ----------------
__global__ void k_topk(const float* __restrict__ IW, float* __restrict__ out)
{
    extern __shared__ char sm[];
    float* sw   = (float*)sm;                                // NPAIR floats
    float* rw   = (float*)(sm + NPAIR*4);                    // 1024
    int*   rp   = (int*)  (sm + NPAIR*4 + 4096);             // 1024
    int*   sel  = (int*)  (sm + NPAIR*4 + 8192);             // 20
    float* vsel = (float*)(sm + NPAIR*4 + 8192 + 80);        // 20
    int tid = threadIdx.x;

    for (int q = tid; q < Fdim*Fdim; q += 1024) {
        int i = q >> 8, j = q & 255;
        if (j > i) {
            int p = i*255 - (i*(i-1))/2 + (j - i - 1);
            sw[p] = IW[q];
        }
    }
    __syncthreads();

    for (int r = 0; r < Kn; r++) {
        float bw = -FLT_MAX; int bp = 1 << 30;
        for (int p = tid; p < NPAIR; p += 1024) {
            bool taken = false;
            for (int t = 0; t < r; t++) taken |= (sel[t] == p);
            if (!taken) {
                float w = sw[p];
                if (w > bw || (w == bw && p < bp)) { bw = w; bp = p; }
            }
        }
        rw[tid] = bw; rp[tid] = bp;
        __syncthreads();
        for (int s = 512; s > 0; s >>= 1) {
            if (tid < s) {
                float w2 = rw[tid+s]; int p2 = rp[tid+s];
                if (w2 > rw[tid] || (w2 == rw[tid] && p2 < rp[tid])) { rw[tid] = w2; rp[tid] = p2; }
            }
            __syncthreads();
        }
        if (tid == 0) sel[r] = rp[0];
        __syncthreads();
    }

    if (tid < Kn) {
        int p = sel[tid];
        int rem = p, i = 0;
        while (rem >= 255 - i) { rem -= 255 - i; i++; }
        int j = i + 1 + rem;
        g_pi[tid] = i; g_pj[tid] = j;
        float v = 1.0f / (1.0f + expf(-sw[p]));
        vsel[tid] = v;
        out[BK + tid] = v;                                   // importances
        out[BK + 2*Kn + 1 + 2*tid]     = (float)i;           // selected_pairs
        out[BK + 2*Kn + 1 + 2*tid + 1] = (float)j;
    }
    __syncthreads();
    if (tid == 0) {
        int cnt = 0;
        for (int t = 0; t < Kn; t++) cnt += (vsel[t] > 0.1f);
        out[BK + 2*Kn] = (float)cnt;                         // active_interactions
    }
}

// ---------------- kernel A: ctx network + pair gather (512 thr) ----------------
__global__ void __launch_bounds__(512,1) k_ctx(
    const float* __restrict__ x,   const float* __restrict__ Wc1,
    const float* __restrict__ bc1, const float* __restrict__ Wc2,
    const float* __restrict__ bc2)
{
    extern __shared__ char sm[];
    float* Wc1s = (float*)sm;            // 16384
    float* xs   = Wc1s + 16384;          // 256*66 = 16896 (transposed [f][r], pad 66)
    float* hs   = xs + 16896;            // 64*65 = 4160
    float* Wc2s = hs + 4160;             // 1280
    float* ctxs = Wc2s + 1280;           // 1280
    float* bc1s = ctxs + 1280;           // 64
    float* bc2s = bc1s + 64;             // 20
    float* bsum = bc2s + 20;             // 20
    int*   pcols = (int*)(bsum + 20);    // 40

    int tid = threadIdx.x;
    for (int idx = tid; idx < Fdim*Hn; idx += 512) Wc1s[idx] = Wc1[idx];
    for (int idx = tid; idx < Hn*Kn;  idx += 512) Wc2s[idx] = Wc2[idx];
    if (tid < Hn)   bc1s[tid] = bc1[tid];
    if (tid < Kn) { bc2s[tid] = bc2[tid]; bsum[tid] = 0.0f; }
    if (tid < 2*Kn) pcols[tid] = (tid & 1) ? g_pj[tid>>1] : g_pi[tid>>1];
    __syncthreads();

    int tr = tid >> 4, tc = tid & 15;    // tr 0..31 (2 rows), tc 0..15 (4 cols)
    int f0 = tid & 255, half = tid >> 8; // for x staging
    for (int tile = blockIdx.x; tile < Bn/TILE_A; tile += GRID_A) {
        int b0 = tile * TILE_A;
        // stage x tile, transposed: xs[f][r]
        #pragma unroll 4
        for (int ii = 0; ii < 32; ii++) {
            int r = half*32 + ii;
            xs[f0*66 + r] = x[(b0 + r)*Fdim + f0];
        }
        __syncthreads();

        // GEMM1: thread computes 2 rows x 4 cols
        float acc[2][4];
        #pragma unroll
        for (int i = 0; i < 2; i++)
            #pragma unroll
            for (int j = 0; j < 4; j++) acc[i][j] = 0.f;

        #pragma unroll 4
        for (int f = 0; f < Fdim; f++) {
            float2 a  = *(float2*)&xs[f*66 + tr*2];
            float4 bv = *(float4*)&Wc1s[f*64 + tc*4];
            acc[0][0] += a.x*bv.x; acc[0][1] += a.x*bv.y; acc[0][2] += a.x*bv.z; acc[0][3] += a.x*bv.w;
            acc[1][0] += a.y*bv.x; acc[1][1] += a.y*bv.y; acc[1][2] += a.y*bv.z; acc[1][3] += a.y*bv.w;
        }
        #pragma unroll
        for (int i = 0; i < 2; i++)
            #pragma unroll
            for (int j = 0; j < 4; j++)
                hs[(tr*2+i)*65 + tc*4+j] = fmaxf(acc[i][j] + bc1s[tc*4+j], 0.f);
        __syncthreads();

        // layer 2 + sigmoid: ctx[64][20]
        for (int idx = tid; idx < TILE_A*Kn; idx += 512) {
            int r = idx / Kn, k = idx - r*Kn;
            float s = bc2s[k];
            #pragma unroll 8
            for (int h = 0; h < Hn; h++) s += hs[r*65 + h] * Wc2s[h*Kn + k];
            ctxs[idx] = 1.0f / (1.0f + expf(-s));
        }
        __syncthreads();

        // coalesced k-major ctx write
        for (int idx = tid; idx < TILE_A*Kn; idx += 512) {
            int kk = idx >> 6, r = idx & 63;
            g_ctx[kk*Bn + b0 + r] = ctxs[r*Kn + kk];
        }
        // coalesced c-major pair gather
        #pragma unroll
        for (int ii = 0; ii < 5; ii++) {
            int idx = tid + 512*ii;          // < 2560
            int c = idx >> 6, r = idx & 63;
            g_pairs[c*Bn + b0 + r] = xs[pcols[c]*66 + r];
        }
        // ctx mean partials
        if (tid < Kn) {
            float s = 0.f;
            for (int r = 0; r < TILE_A; r++) s += ctxs[r*Kn + tid];
            bsum[tid] += s;
        }
        __syncthreads();
    }
    if (tid < Kn) g_partial[blockIdx.x*Kn + tid] = bsum[tid];
}

// ---------------- kernel C: ctx mean finalize ----------------
__global__ void k_mean(float* __restrict__ out)
{
    int t = threadIdx.x;
    if (t < Kn) {
        double s = 0.0;
        for (int i = 0; i < GRID_A; i++) s += (double)g_partial[i*Kn + t];
        out[BK + Kn + t] = (float)(s / (double)Bn);
    }
}

// ---------------- kernel B: K stacked pair MLPs (512 thr, W2 in 2 k-chunks) ----------------
__global__ void __launch_bounds__(512,1) k_mlp(
    const float* __restrict__ W1, const float* __restrict__ b1,
    const float* __restrict__ W2, const float* __restrict__ b2,
    const float* __restrict__ W3, const float* __restrict__ b3,
    float* __restrict__ out)
{
    extern __shared__ char sm[];
    float* W2s  = (float*)sm;        // KCHUNK*2048 = 20480
    float* h1s  = W2s + 20480;       // 64*256 = 16384 ([h][r])
    float* outs = h1s + 16384;       // 256*10 = 2560
    float* W1s  = outs + 2560;       // 2560
    float* b1s  = W1s + 2560;        // 1280
    float* b2s  = b1s + 1280;        // 640
    float* W3s  = b2s + 640;         // 640
    float* b3s  = W3s + 640;         // 20

    int tid = threadIdx.x;
    for (int idx = tid; idx < Kn*2*Hn;  idx += 512) W1s[idx] = W1[idx];
    for (int idx = tid; idx < Kn*Hn;    idx += 512) b1s[idx] = b1[idx];
    for (int idx = tid; idx < Kn*Mn;    idx += 512) { b2s[idx] = b2[idx]; W3s[idx] = W3[idx]; }
    if (tid < Kn) b3s[tid] = b3[tid];

    int mg = tid & 3, rg = tid >> 2;     // 4 m-groups x 128 row-groups
    int m0 = mg * 8,  r0 = rg * 2;       // rows 0..255, m 0..31
    int rr = tid & 255, hh = tid >> 8;   // for h1 stage

    for (int c = 0; c < 2; c++) {
        int koff = c * KCHUNK;
        __syncthreads();                 // protect W2s reuse across chunks
        for (int idx = tid; idx < KCHUNK*Hn*Mn; idx += 512)
            W2s[idx] = W2[koff*Hn*Mn + idx];
        __syncthreads();

        for (int tile = blockIdx.x; tile < Bn/TILE_B; tile += GRID_B) {
            int b0 = tile * TILE_B;
            for (int kk = 0; kk < KCHUNK; kk++) {
                int k = koff + kk;
                // h1[h][r] = relu(p0*W1[k,0,h] + p1*W1[k,1,h] + b1[k,h])
                {
                    float p0 = g_pairs[(2*k)*Bn   + b0 + rr];
                    float p1 = g_pairs[(2*k+1)*Bn + b0 + rr];
                    const float* W1k = W1s + k*128;
                    const float* b1k = b1s + k*64;
                    #pragma unroll 8
                    for (int ii = 0; ii < 32; ii++) {
                        int h = hh*32 + ii;
                        float v = fmaf(p0, W1k[h], fmaf(p1, W1k[64 + h], b1k[h]));
                        h1s[h*256 + rr] = fmaxf(v, 0.f);
                    }
                }
                __syncthreads();
                // GEMM: C[256][32] = h1s^T @ W2[k]; thread = 2 rows x 8 m
                float acc[2][8];
                #pragma unroll
                for (int j = 0; j < 8; j++) { acc[0][j] = 0.f; acc[1][j] = 0.f; }
                const float* W2k = W2s + kk*2048;
                #pragma unroll 4
                for (int h = 0; h < Hn; h++) {
                    float2 a  = *(float2*)&h1s[h*256 + r0];
                    float4 w0 = *(float4*)&W2k[h*32 + m0];
                    float4 w1 = *(float4*)&W2k[h*32 + m0 + 4];
                    acc[0][0] += a.x*w0.x; acc[0][1] += a.x*w0.y; acc[0][2] += a.x*w0.z; acc[0][3] += a.x*w0.w;
                    acc[0][4] += a.x*w1.x; acc[0][5] += a.x*w1.y; acc[0][6] += a.x*w1.z; acc[0][7] += a.x*w1.w;
                    acc[1][0] += a.y*w0.x; acc[1][1] += a.y*w0.y; acc[1][2] += a.y*w0.z; acc[1][3] += a.y*w0.w;
                    acc[1][4] += a.y*w1.x; acc[1][5] += a.y*w1.y; acc[1][6] += a.y*w1.z; acc[1][7] += a.y*w1.w;
                }
                // epilogue: relu(+b2), dot W3, quad-reduce, + b3, * ctx
                float s0 = 0.f, s1 = 0.f;
                #pragma unroll
                for (int j = 0; j < 8; j++) {
                    float bb = b2s[k*32 + m0 + j];
                    float w3 = W3s[k*32 + m0 + j];
                    s0 += fmaxf(acc[0][j] + bb, 0.f) * w3;
                    s1 += fmaxf(acc[1][j] + bb, 0.f) * w3;
                }
                s0 += __shfl_xor_sync(0xffffffffu, s0, 1);
                s0 += __shfl_xor_sync(0xffffffffu, s0, 2);
                s1 += __shfl_xor_sync(0xffffffffu, s1, 1);
                s1 += __shfl_xor_sync(0xffffffffu, s1, 2);
                if (mg == 0) {
                    float2 c2 = *(float2*)&g_ctx[k*Bn + b0 + r0];
                    float bb3 = b3s[k];
                    outs[r0*KCHUNK + kk]     = (s0 + bb3) * c2.x;
                    outs[(r0+1)*KCHUNK + kk] = (s1 + bb3) * c2.y;
                }
                __syncthreads();     // h1s / outs reuse
            }
            // write this chunk's outputs: out[(b0+r)*20 + koff + kk]
            #pragma unroll
            for (int ii = 0; ii < 5; ii++) {
                int idx = tid + 512*ii;              // < 2560
                int r = idx / KCHUNK, kk = idx - r*KCHUNK;
                out[(b0 + r)*Kn + koff + kk] = outs[idx];
            }
            __syncthreads();
        }
    }
}

// ---------------- launch ----------------
extern "C" void kernel_launch(void* const* d_in, const int* in_sizes, int n_in,
                              void* d_out, int out_size)
{
    const float* x   = (const float*)d_in[0];
    const float* IW  = (const float*)d_in[1];
    const float* Wc1 = (const float*)d_in[2];
    const float* bc1 = (const float*)d_in[3];
    const float* Wc2 = (const float*)d_in[4];
    const float* bc2 = (const float*)d_in[5];
    const float* W1  = (const float*)d_in[6];
    const float* b1  = (const float*)d_in[7];
    const float* W2  = (const float*)d_in[8];
    const float* b2  = (const float*)d_in[9];
    const float* W3  = (const float*)d_in[10];
    const float* b3  = (const float*)d_in[11];
    float* out = (float*)d_out;

    const int smem0 = NPAIR*4 + 4096 + 4096 + 80 + 80;   // 138,912 B
    const int smemA = 40144 * 4;                          // 160,576 B
    const int smemB = 44564 * 4;                          // 178,256 B

    cudaFuncSetAttribute(k_topk, cudaFuncAttributeMaxDynamicSharedMemorySize, smem0);
    cudaFuncSetAttribute(k_ctx,  cudaFuncAttributeMaxDynamicSharedMemorySize, smemA);
    cudaFuncSetAttribute(k_mlp,  cudaFuncAttributeMaxDynamicSharedMemorySize, smemB);

    // order chosen so the fixed ncu skip window lands on k_mlp (was k_mean)
    k_topk<<<1, 1024, smem0>>>(IW, out);
    k_ctx <<<GRID_A, 512, smemA>>>(x, Wc1, bc1, Wc2, bc2);
    k_mean<<<1, 32>>>(out);
    k_mlp <<<GRID_B, 512, smemB>>>(W1, b1, W2, b2, W3, b3, out);
}